// round 10
// baseline (speedup 1.0000x reference)
#include <cuda_runtime.h>
#include <cuda_bf16.h>
#include <math.h>
#include <stdint.h>

#define BB 8
#define SS 2048
#define DD 256
#define RR (BB*SS)          // 16384 rows total
#define NEG_INF -1.0e30f

// ----- HMMA sim tiling -----
#define TS2 128
#define NT2 (SS/TS2)                 // 16
#define TRI2 (NT2*(NT2+1)/2)         // 136
#define KC 64
#define NCHUNK (DD/KC)               // 4
#define LDA 72                       // padded smem row stride (bf16 elems)
#define TILE_B (128*LDA*2)           // 18432 bytes per operand tile
#define SIM_SMEM (4*TILE_B)          // 73728 (also covers Cs 128*132*4=67584)

#define NCAND 8

// ----- HMMA out tiling -----
#define KF (2*DD)                    // 512
#define OUT_A_B (128*LDA*2)          // 18432
#define OUT_B_B (64*LDA*2)           // 9216
#define OUT_SMEM (2*OUT_A_B + 2*OUT_B_B)   // 55296

// ---------------- static scratch ----------------
__device__ float    g_nrm[(size_t)RR*DD];            // 16 MB exact normalized rows
__device__ __nv_bfloat16 g_hi[(size_t)RR*DD];        // 8 MB
__device__ __nv_bfloat16 g_lo[(size_t)RR*DD];        // 8 MB
__device__ float    g_sim[(size_t)BB*SS*SS];         // 134 MB (approx, rank-only)
__device__ int      g_top[(size_t)RR*3];
__device__ unsigned g_mask[(size_t)RR*(SS/32)];      // 4 MB
__device__ __nv_bfloat16 g_chi[(size_t)RR*KF];       // 16 MB combined hi
__device__ __nv_bfloat16 g_clo[(size_t)RR*KF];       // 16 MB combined lo
__device__ __nv_bfloat16 g_whi[(size_t)DD*KF];       // 256 KB
__device__ __nv_bfloat16 g_wlo[(size_t)DD*KF];       // 256 KB
__device__ float    g_y[(size_t)RR*DD];              // 16 MB

__device__ __forceinline__ uint32_t smem_u32(const void* p) {
    uint32_t a;
    asm("{ .reg .u64 t; cvta.to.shared.u64 t, %1; cvt.u32.u64 %0, t; }" : "=r"(a) : "l"(p));
    return a;
}
__device__ __forceinline__ void ldmx4(uint32_t* r, uint32_t addr) {
    asm volatile("ldmatrix.sync.aligned.m8n8.x4.shared.b16 {%0,%1,%2,%3}, [%4];"
        : "=r"(r[0]), "=r"(r[1]), "=r"(r[2]), "=r"(r[3]) : "r"(addr));
}
__device__ __forceinline__ void mma16816(float* c, const uint32_t* a, uint32_t b0, uint32_t b1) {
    asm volatile("mma.sync.aligned.m16n8k16.row.col.f32.bf16.bf16.f32 "
        "{%0,%1,%2,%3}, {%4,%5,%6,%7}, {%8,%9}, {%0,%1,%2,%3};"
        : "+f"(c[0]), "+f"(c[1]), "+f"(c[2]), "+f"(c[3])
        : "r"(a[0]), "r"(a[1]), "r"(a[2]), "r"(a[3]), "r"(b0), "r"(b1));
}

// ---------------- 1. row L2-normalize -> fp32 + bf16 hi/lo; raw x -> combined[0:256] ----------------
__global__ void k_norm(const float* __restrict__ x) {
    int row = blockIdx.x;
    int t = threadIdx.x;
    float v = x[(size_t)row*DD + t];
    __shared__ float sh[8];
    float s = v*v;
    #pragma unroll
    for (int o = 16; o > 0; o >>= 1) s += __shfl_xor_sync(0xffffffffu, s, o);
    if ((t & 31) == 0) sh[t >> 5] = s;
    __syncthreads();
    if (t < 32) {
        float z = (t < 8) ? sh[t] : 0.f;
        #pragma unroll
        for (int o = 4; o > 0; o >>= 1) z += __shfl_xor_sync(0xffffffffu, z, o);
        if (t == 0) sh[0] = z;
    }
    __syncthreads();
    float nrm = sqrtf(sh[0]);
    float sc = 1.f / fmaxf(nrm, 1e-12f);
    float nv = v * sc;
    __nv_bfloat16 h = __float2bfloat16(nv);
    float lo = nv - __bfloat162float(h);
    g_nrm[(size_t)row*DD + t] = nv;
    g_hi[(size_t)row*DD + t] = h;
    g_lo[(size_t)row*DD + t] = __float2bfloat16(lo);
    __nv_bfloat16 xh = __float2bfloat16(v);
    g_chi[(size_t)row*KF + t] = xh;
    g_clo[(size_t)row*KF + t] = __float2bfloat16(v - __bfloat162float(xh));
}

// ---------------- 1b. W hi/lo split ----------------
__global__ void k_wsplit(const float* __restrict__ W) {
    int t = blockIdx.x*256 + threadIdx.x;   // DD*KF = 131072
    float v = W[t];
    __nv_bfloat16 h = __float2bfloat16(v);
    g_whi[t] = h;
    g_wlo[t] = __float2bfloat16(v - __bfloat162float(h));
}

// ---------------- 2. approx sim = nrm @ nrm^T via bf16 HMMA 3-split ----------------
__global__ void __launch_bounds__(256, 2) k_sim3() {
    extern __shared__ char smem[];
    uint32_t sb = smem_u32(smem);
    int tid = threadIdx.x;
    int lane = tid & 31, wid = tid >> 5;
    int wm = wid & 3, wn = wid >> 2;

    int t = blockIdx.x;
    int bi = 0;
    while ((bi+1)*(bi+2)/2 <= t) bi++;
    int bj = t - bi*(bi+1)/2;           // bi >= bj
    int b = blockIdx.y;
    int rA = bi*TS2, rB = bj*TS2;

    const __nv_bfloat16* hib = g_hi + (size_t)b*SS*DD;
    const __nv_bfloat16* lob = g_lo + (size_t)b*SS*DD;

    const uint32_t AH = sb, AL = sb + TILE_B, BH = sb + 2*TILE_B, BL = sb + 3*TILE_B;

    float acc[2][8][4];
    #pragma unroll
    for (int i = 0; i < 2; i++)
        #pragma unroll
        for (int j = 0; j < 8; j++)
            #pragma unroll
            for (int q = 0; q < 4; q++) acc[i][j][q] = 0.f;

    int ar = lane & 15, aseg = lane >> 4;
    int br = lane & 7, bsel = lane >> 3;
    int bnoff = (bsel >> 1) * 8, bkoff = (bsel & 1) * 8;

    int lrow = tid >> 1, lcol = (tid & 1) * 32;

    for (int c = 0; c < NCHUNK; c++) {
        int kk = c * KC;
        {
            const uint4* pAh = (const uint4*)(hib + (size_t)(rA+lrow)*DD + kk + lcol);
            const uint4* pAl = (const uint4*)(lob + (size_t)(rA+lrow)*DD + kk + lcol);
            const uint4* pBh = (const uint4*)(hib + (size_t)(rB+lrow)*DD + kk + lcol);
            const uint4* pBl = (const uint4*)(lob + (size_t)(rB+lrow)*DD + kk + lcol);
            uint32_t so = (uint32_t)(lrow*LDA + lcol) * 2;
            #pragma unroll
            for (int q = 0; q < 4; q++) {
                *(uint4*)(smem + (AH - sb) + so + q*16) = pAh[q];
                *(uint4*)(smem + (AL - sb) + so + q*16) = pAl[q];
                *(uint4*)(smem + (BH - sb) + so + q*16) = pBh[q];
                *(uint4*)(smem + (BL - sb) + so + q*16) = pBl[q];
            }
        }
        __syncthreads();

        #pragma unroll
        for (int ks = 0; ks < KC/16; ks++) {
            int kb = ks * 16;
            uint32_t ah[2][4], al[2][4];
            #pragma unroll
            for (int mt = 0; mt < 2; mt++) {
                uint32_t ao = (uint32_t)((wm*32 + mt*16 + ar)*LDA + kb + aseg*8) * 2;
                ldmx4(ah[mt], AH + ao);
                ldmx4(al[mt], AL + ao);
            }
            #pragma unroll
            for (int np = 0; np < 4; np++) {
                uint32_t bo = (uint32_t)((wn*64 + np*16 + bnoff + br)*LDA + kb + bkoff) * 2;
                uint32_t bh[4], bl[4];
                ldmx4(bh, BH + bo);
                ldmx4(bl, BL + bo);
                #pragma unroll
                for (int mt = 0; mt < 2; mt++) {
                    #pragma unroll
                    for (int sub = 0; sub < 2; sub++) {
                        int nt = np*2 + sub;
                        mma16816(acc[mt][nt], ah[mt], bh[sub*2], bh[sub*2+1]);
                        mma16816(acc[mt][nt], ah[mt], bl[sub*2], bl[sub*2+1]);
                        mma16816(acc[mt][nt], al[mt], bh[sub*2], bh[sub*2+1]);
                    }
                }
            }
        }
        __syncthreads();
    }

    float* simb = g_sim + (size_t)b*SS*SS;
    int fr = lane >> 2, fc = (lane & 3) * 2;

    #pragma unroll
    for (int mt = 0; mt < 2; mt++) {
        #pragma unroll
        for (int nt = 0; nt < 8; nt++) {
            int r0 = rA + wm*32 + mt*16 + fr;
            int cc = rB + wn*64 + nt*8 + fc;
            *(float2*)(simb + (size_t)r0*SS + cc)     = make_float2(acc[mt][nt][0], acc[mt][nt][1]);
            *(float2*)(simb + (size_t)(r0+8)*SS + cc) = make_float2(acc[mt][nt][2], acc[mt][nt][3]);
        }
    }

    if (bi != bj) {
        float* Cs = (float*)smem;   // reuse: [col][row], stride 132
        __syncthreads();
        #pragma unroll
        for (int mt = 0; mt < 2; mt++) {
            #pragma unroll
            for (int nt = 0; nt < 8; nt++) {
                int r0 = wm*32 + mt*16 + fr;
                int cc = wn*64 + nt*8 + fc;
                Cs[(cc+0)*132 + r0]   = acc[mt][nt][0];
                Cs[(cc+1)*132 + r0]   = acc[mt][nt][1];
                Cs[(cc+0)*132 + r0+8] = acc[mt][nt][2];
                Cs[(cc+1)*132 + r0+8] = acc[mt][nt][3];
            }
        }
        __syncthreads();
        for (int w = tid; w < 128*32; w += 256) {
            int n = w >> 5, m4 = (w & 31) * 4;
            float4 v = make_float4(Cs[n*132 + m4], Cs[n*132 + m4 + 1],
                                   Cs[n*132 + m4 + 2], Cs[n*132 + m4 + 3]);
            *(float4*)(simb + (size_t)(rB + n)*SS + rA + m4) = v;
        }
    }
}

// ---------------- 3. warp-per-row single-pass top-8 + exact rescore -> top-3 ----------------
// grid: RR/8 blocks, 256 threads (8 warps), one row per warp
__global__ void __launch_bounds__(256) k_top3() {
    __shared__ float svv[8][256];
    __shared__ int   svi[8][256];
    __shared__ int   cand[8][NCAND];
    __shared__ float ex[8][NCAND];

    int tid = threadIdx.x;
    int lane = tid & 31, wid = tid >> 5;
    int row = blockIdx.x*8 + wid;
    int b = row / SS, i = row % SS;
    const float* srow = g_sim + (size_t)b*SS*SS + (size_t)i*SS;

    float val[NCAND];
    int   idx[NCAND];
    #pragma unroll
    for (int p = 0; p < NCAND; p++) { val[p] = NEG_INF; idx[p] = SS; }

    // stream 64 elements per lane (16 x float4), guarded register insert
    #pragma unroll 4
    for (int q = 0; q < 16; q++) {
        int jb = q*128 + lane*4;
        float4 vv = *(const float4*)(srow + jb);
        #pragma unroll
        for (int e = 0; e < 4; e++) {
            float v = (e == 0) ? vv.x : (e == 1) ? vv.y : (e == 2) ? vv.z : vv.w;
            int j = jb + e;
            if (j == i) continue;
            if (v > val[NCAND-1]) {
                #pragma unroll
                for (int p = NCAND-1; p >= 1; p--) {
                    bool gprev = v > val[p-1];
                    bool gcur  = (p == NCAND-1) ? true : (v > val[p]);
                    float nv = gprev ? val[p-1] : (gcur ? v : val[p]);
                    int   ni = gprev ? idx[p-1] : (gcur ? j : idx[p]);
                    val[p] = nv; idx[p] = ni;
                }
                if (v > val[0]) { val[0] = v; idx[0] = j; }
            }
        }
    }

    // dump lane-local top-8 to smem
    #pragma unroll
    for (int p = 0; p < NCAND; p++) {
        svv[wid][lane*NCAND + p] = val[p];
        svi[wid][lane*NCAND + p] = idx[p];
    }
    __syncwarp();

    // 8 warp-argmax passes over the 256 candidates
    for (int p = 0; p < NCAND; p++) {
        float bv = NEG_INF; int bidx = SS; int bslot = -1;
        #pragma unroll
        for (int k = 0; k < NCAND; k++) {
            int slot = lane*NCAND + k;
            float v = svv[wid][slot];
            int   jx = svi[wid][slot];
            if (v > bv || (v == bv && jx < bidx)) { bv = v; bidx = jx; bslot = slot; }
        }
        #pragma unroll
        for (int o = 16; o > 0; o >>= 1) {
            float ov = __shfl_xor_sync(0xffffffffu, bv, o);
            int   oi = __shfl_xor_sync(0xffffffffu, bidx, o);
            int   os = __shfl_xor_sync(0xffffffffu, bslot, o);
            if (ov > bv || (ov == bv && oi < bidx)) { bv = ov; bidx = oi; bslot = os; }
        }
        if (lane == (bslot >> 3)) svv[wid][bslot] = NEG_INF;   // one lane owns the slot
        if (lane == 0) cand[wid][p] = bidx;
        __syncwarp();
    }

    // exact fp32 rescore of the 8 candidates (warp-scope dots)
    const float* xi = g_nrm + (size_t)row*DD;
    for (int c = 0; c < NCAND; c++) {
        int j = cand[wid][c];
        const float* xj = g_nrm + ((size_t)b*SS + j)*DD;
        float s = 0.f;
        #pragma unroll
        for (int q = 0; q < DD/32; q++) s += xi[lane + q*32] * xj[lane + q*32];
        #pragma unroll
        for (int o = 16; o > 0; o >>= 1) s += __shfl_xor_sync(0xffffffffu, s, o);
        if (lane == 0) ex[wid][c] = s;
    }
    __syncwarp();

    if (lane == 0) {
        bool used[NCAND] = {};
        for (int p = 0; p < 3; p++) {
            float bv = NEG_INF; int bc = -1;
            for (int c = 0; c < NCAND; c++) {
                if (used[c]) continue;
                if (bc < 0 || ex[wid][c] > bv) { bv = ex[wid][c]; bc = c; }
            }
            used[bc] = true;
            g_top[(size_t)row*3 + p] = cand[wid][bc];
        }
    }
}

// ---------------- 4. adjacency bitmask ----------------
__global__ void k_zmask() {
    int t = blockIdx.x*256 + threadIdx.x;
    if (t < RR*(SS/32)) g_mask[t] = 0u;
}

__global__ void k_edges() {
    int t = blockIdx.x*256 + threadIdx.x;
    if (t >= RR*3) return;
    int row = t / 3;
    int j = g_top[t];
    int b = row / SS, i = row % SS;
    atomicOr(&g_mask[(size_t)row*(SS/32) + (j >> 5)], 1u << (j & 31));
    atomicOr(&g_mask[((size_t)b*SS + j)*(SS/32) + (i >> 5)], 1u << (i & 31));
}

// ---------------- 5. neighbor aggregation -> combined[256:512] hi/lo ----------------
__global__ void k_agg(const float* __restrict__ x) {
    int row = blockIdx.x;
    int b = row / SS, i = row % SS;
    __shared__ int   sj[128];
    __shared__ float sw[128];
    __shared__ int   cnt;
    int t = threadIdx.x;
    int lane = t & 31, wid = t >> 5;
    if (t == 0) cnt = 0;
    __syncthreads();
    if (t < SS/32) {
        unsigned w = g_mask[(size_t)row*(SS/32) + t];
        while (w) {
            int bpos = __ffs(w) - 1;
            w &= w - 1;
            int j = t*32 + bpos;
            int p = atomicAdd(&cnt, 1);
            if (p < 128) sj[p] = j;
        }
    }
    __syncthreads();
    int n = min(cnt, 128);

    const float* xi = g_nrm + (size_t)row*DD;
    for (int l = wid; l < n; l += 8) {
        const float* xj = g_nrm + ((size_t)b*SS + sj[l])*DD;
        float s = 0.f;
        #pragma unroll
        for (int q = 0; q < DD/32; q++) s += xi[lane + q*32] * xj[lane + q*32];
        #pragma unroll
        for (int o = 16; o > 0; o >>= 1) s += __shfl_xor_sync(0xffffffffu, s, o);
        if (lane == 0) sw[l] = s;
    }
    __syncthreads();

    float csum = 0.f;
    for (int l = 0; l < n; l++) csum += sw[l];
    float acc = 0.f;
    for (int l = 0; l < n; l++)
        acc += sw[l] * x[((size_t)b*SS + sj[l])*DD + t];
    float mval = acc / fmaxf(csum, 1.0f);
    __nv_bfloat16 h = __float2bfloat16(mval);
    g_chi[(size_t)row*KF + DD + t] = h;
    g_clo[(size_t)row*KF + DD + t] = __float2bfloat16(mval - __bfloat162float(h));
}

// ---------------- 6. projection GEMM via bf16 HMMA 3-split + bias + residual ----------------
__global__ void __launch_bounds__(256, 2) k_out2(const float* __restrict__ x,
                                                 const float* __restrict__ bias) {
    extern __shared__ char smem[];
    uint32_t sb = smem_u32(smem);
    int tid = threadIdx.x;
    int lane = tid & 31, wid = tid >> 5;
    int wm = wid & 3, wn = wid >> 2;        // 4 x 2 warps, warp tile 32x32

    int bx = blockIdx.x;
    int rA = (bx >> 2) * 128, cB = (bx & 3) * 64;

    const uint32_t AH = sb, AL = sb + OUT_A_B, BH = sb + 2*OUT_A_B, BL = sb + 2*OUT_A_B + OUT_B_B;

    float acc[2][4][4];
    #pragma unroll
    for (int i = 0; i < 2; i++)
        #pragma unroll
        for (int j = 0; j < 4; j++)
            #pragma unroll
            for (int q = 0; q < 4; q++) acc[i][j][q] = 0.f;

    int ar = lane & 15, aseg = lane >> 4;
    int br = lane & 7, bsel = lane >> 3;
    int bnoff = (bsel >> 1) * 8, bkoff = (bsel & 1) * 8;

    int lrow = tid >> 1, lcol = (tid & 1) * 32;

    for (int c = 0; c < KF/KC; c++) {       // 8 chunks of 64
        int kk = c * KC;
        {
            const uint4* pAh = (const uint4*)(g_chi + (size_t)(rA+lrow)*KF + kk + lcol);
            const uint4* pAl = (const uint4*)(g_clo + (size_t)(rA+lrow)*KF + kk + lcol);
            uint32_t so = (uint32_t)(lrow*LDA + lcol) * 2;
            #pragma unroll
            for (int q = 0; q < 4; q++) {
                *(uint4*)(smem + (AH - sb) + so + q*16) = pAh[q];
                *(uint4*)(smem + (AL - sb) + so + q*16) = pAl[q];
            }
            if (tid < 128) {
                const uint4* pBh = (const uint4*)(g_whi + (size_t)(cB+lrow)*KF + kk + lcol);
                const uint4* pBl = (const uint4*)(g_wlo + (size_t)(cB+lrow)*KF + kk + lcol);
                #pragma unroll
                for (int q = 0; q < 4; q++) {
                    *(uint4*)(smem + (BH - sb) + so + q*16) = pBh[q];
                    *(uint4*)(smem + (BL - sb) + so + q*16) = pBl[q];
                }
            }
        }
        __syncthreads();

        #pragma unroll
        for (int ks = 0; ks < KC/16; ks++) {
            int kb = ks * 16;
            uint32_t ah[2][4], al[2][4];
            #pragma unroll
            for (int mt = 0; mt < 2; mt++) {
                uint32_t ao = (uint32_t)((wm*32 + mt*16 + ar)*LDA + kb + aseg*8) * 2;
                ldmx4(ah[mt], AH + ao);
                ldmx4(al[mt], AL + ao);
            }
            #pragma unroll
            for (int np = 0; np < 2; np++) {
                uint32_t bo = (uint32_t)((wn*32 + np*16 + bnoff + br)*LDA + kb + bkoff) * 2;
                uint32_t bh[4], bl[4];
                ldmx4(bh, BH + bo);
                ldmx4(bl, BL + bo);
                #pragma unroll
                for (int mt = 0; mt < 2; mt++) {
                    #pragma unroll
                    for (int sub = 0; sub < 2; sub++) {
                        int nt = np*2 + sub;
                        mma16816(acc[mt][nt], ah[mt], bh[sub*2], bh[sub*2+1]);
                        mma16816(acc[mt][nt], ah[mt], bl[sub*2], bl[sub*2+1]);
                        mma16816(acc[mt][nt], al[mt], bh[sub*2], bh[sub*2+1]);
                    }
                }
            }
        }
        __syncthreads();
    }

    int fr = lane >> 2, fc = (lane & 3) * 2;
    #pragma unroll
    for (int mt = 0; mt < 2; mt++) {
        #pragma unroll
        for (int nt = 0; nt < 4; nt++) {
            int r0 = rA + wm*32 + mt*16 + fr;
            int cc = cB + wn*32 + nt*8 + fc;
            g_y[(size_t)r0*DD + cc]       = x[(size_t)r0*DD + cc]       + acc[mt][nt][0] + bias[cc];
            g_y[(size_t)r0*DD + cc+1]     = x[(size_t)r0*DD + cc+1]     + acc[mt][nt][1] + bias[cc+1];
            g_y[(size_t)(r0+8)*DD + cc]   = x[(size_t)(r0+8)*DD + cc]   + acc[mt][nt][2] + bias[cc];
            g_y[(size_t)(r0+8)*DD + cc+1] = x[(size_t)(r0+8)*DD + cc+1] + acc[mt][nt][3] + bias[cc+1];
        }
    }
}

// ---------------- 7. LayerNorm ----------------
__global__ void k_ln(const float* __restrict__ gamma, const float* __restrict__ beta,
                     float* __restrict__ out) {
    int row = blockIdx.x;
    int t = threadIdx.x;
    float v = g_y[(size_t)row*DD + t];
    __shared__ float sh[8];

    float s = v;
    #pragma unroll
    for (int o = 16; o > 0; o >>= 1) s += __shfl_xor_sync(0xffffffffu, s, o);
    if ((t & 31) == 0) sh[t >> 5] = s;
    __syncthreads();
    if (t < 32) {
        float z = (t < 8) ? sh[t] : 0.f;
        #pragma unroll
        for (int o = 4; o > 0; o >>= 1) z += __shfl_xor_sync(0xffffffffu, z, o);
        if (t == 0) sh[0] = z;
    }
    __syncthreads();
    float mu = sh[0] * (1.0f/DD);
    __syncthreads();

    float d = v - mu;
    float s2 = d*d;
    #pragma unroll
    for (int o = 16; o > 0; o >>= 1) s2 += __shfl_xor_sync(0xffffffffu, s2, o);
    if ((t & 31) == 0) sh[t >> 5] = s2;
    __syncthreads();
    if (t < 32) {
        float z = (t < 8) ? sh[t] : 0.f;
        #pragma unroll
        for (int o = 4; o > 0; o >>= 1) z += __shfl_xor_sync(0xffffffffu, z, o);
        if (t == 0) sh[0] = z;
    }
    __syncthreads();
    float var = sh[0] * (1.0f/DD);

    out[(size_t)row*DD + t] = d * rsqrtf(var + 1e-5f) * gamma[t] + beta[t];
}

// ---------------- launch ----------------
extern "C" void kernel_launch(void* const* d_in, const int* in_sizes, int n_in,
                              void* d_out, int out_size) {
    const float* x     = (const float*)d_in[0];
    const float* W     = (const float*)d_in[1];
    const float* bias  = (const float*)d_in[2];
    const float* gamma = (const float*)d_in[3];
    const float* beta  = (const float*)d_in[4];
    float* out = (float*)d_out;

    cudaFuncSetAttribute(k_sim3, cudaFuncAttributeMaxDynamicSharedMemorySize, SIM_SMEM);
    cudaFuncSetAttribute(k_out2, cudaFuncAttributeMaxDynamicSharedMemorySize, OUT_SMEM);

    k_norm<<<RR, 256>>>(x);
    k_wsplit<<<(DD*KF)/256, 256>>>(W);
    k_sim3<<<dim3(TRI2, BB), 256, SIM_SMEM>>>();
    k_top3<<<RR/8, 256>>>();
    k_zmask<<<(RR*(SS/32) + 255)/256, 256>>>();
    k_edges<<<(RR*3 + 255)/256, 256>>>();
    k_agg<<<RR, 256>>>(x);
    k_out2<<<(RR/128)*4, 256, OUT_SMEM>>>(x, bias);
    k_ln<<<RR, 256>>>(gamma, beta, out);
}

// round 11
// speedup vs baseline: 1.7487x; 1.7487x over previous
#include <cuda_runtime.h>
#include <cuda_bf16.h>
#include <math.h>
#include <stdint.h>

#define BB 8
#define SS 2048
#define DD 256
#define RR (BB*SS)          // 16384 rows total
#define NEG_INF -1.0e30f

// ----- HMMA sim tiling -----
#define TS2 128
#define NT2 (SS/TS2)                 // 16
#define TRI2 (NT2*(NT2+1)/2)         // 136
#define KC 64
#define NCHUNK (DD/KC)               // 4
#define LDA 72                       // padded smem row stride (bf16 elems)
#define TILE_B (128*LDA*2)           // 18432 bytes per operand tile
#define SIM_SMEM (4*TILE_B)          // 73728 (covers key buffer 128*132*4=67584)

#define NCAND 10                     // merge width (rescored exactly)

// ----- HMMA out tiling -----
#define KF (2*DD)                    // 512
#define OUT_A_B (128*LDA*2)          // 18432
#define OUT_B_B (64*LDA*2)           // 9216
#define OUT_SMEM (2*OUT_A_B + 2*OUT_B_B)   // 55296

// ---------------- static scratch ----------------
__device__ float    g_nrm[(size_t)RR*DD];            // 16 MB exact normalized rows
__device__ __nv_bfloat16 g_hi[(size_t)RR*DD];        // 8 MB
__device__ __nv_bfloat16 g_lo[(size_t)RR*DD];        // 8 MB
__device__ uint32_t g_cand[(size_t)RR*256];          // 16.8 MB packed candidate keys
__device__ int      g_top[(size_t)RR*3];
__device__ unsigned g_mask[(size_t)RR*(SS/32)];      // 4 MB
__device__ __nv_bfloat16 g_chi[(size_t)RR*KF];       // 16 MB combined hi
__device__ __nv_bfloat16 g_clo[(size_t)RR*KF];       // 16 MB combined lo
__device__ __nv_bfloat16 g_whi[(size_t)DD*KF];       // 256 KB
__device__ __nv_bfloat16 g_wlo[(size_t)DD*KF];       // 256 KB
__device__ float    g_y[(size_t)RR*DD];              // 16 MB

__device__ __forceinline__ uint32_t smem_u32(const void* p) {
    uint32_t a;
    asm("{ .reg .u64 t; cvta.to.shared.u64 t, %1; cvt.u32.u64 %0, t; }" : "=r"(a) : "l"(p));
    return a;
}
__device__ __forceinline__ void ldmx4(uint32_t* r, uint32_t addr) {
    asm volatile("ldmatrix.sync.aligned.m8n8.x4.shared.b16 {%0,%1,%2,%3}, [%4];"
        : "=r"(r[0]), "=r"(r[1]), "=r"(r[2]), "=r"(r[3]) : "r"(addr));
}
__device__ __forceinline__ void mma16816(float* c, const uint32_t* a, uint32_t b0, uint32_t b1) {
    asm volatile("mma.sync.aligned.m16n8k16.row.col.f32.bf16.bf16.f32 "
        "{%0,%1,%2,%3}, {%4,%5,%6,%7}, {%8,%9}, {%0,%1,%2,%3};"
        : "+f"(c[0]), "+f"(c[1]), "+f"(c[2]), "+f"(c[3])
        : "r"(a[0]), "r"(a[1]), "r"(a[2]), "r"(a[3]), "r"(b0), "r"(b1));
}
// order-preserving float -> uint, top 21 bits kept, 11-bit index packed low
__device__ __forceinline__ uint32_t f2key(float f, int j) {
    uint32_t u = __float_as_uint(f);
    u ^= (uint32_t)((int)u >> 31) | 0x80000000u;
    return (u & 0xFFFFF800u) | (uint32_t)j;
}
// sorted-descending top-8 insert (guarded)
__device__ __forceinline__ void ins8(uint32_t* tk, uint32_t k) {
    if (k > tk[7]) {
        #pragma unroll
        for (int p = 7; p >= 1; p--)
            tk[p] = (k > tk[p-1]) ? tk[p-1] : (k > tk[p] ? k : tk[p]);
        if (k > tk[0]) tk[0] = k;
    }
}

// ---------------- 1. row L2-normalize -> fp32 + bf16 hi/lo; raw x -> combined[0:256] ----------------
__global__ void k_norm(const float* __restrict__ x) {
    int row = blockIdx.x;
    int t = threadIdx.x;
    float v = x[(size_t)row*DD + t];
    __shared__ float sh[8];
    float s = v*v;
    #pragma unroll
    for (int o = 16; o > 0; o >>= 1) s += __shfl_xor_sync(0xffffffffu, s, o);
    if ((t & 31) == 0) sh[t >> 5] = s;
    __syncthreads();
    if (t < 32) {
        float z = (t < 8) ? sh[t] : 0.f;
        #pragma unroll
        for (int o = 4; o > 0; o >>= 1) z += __shfl_xor_sync(0xffffffffu, z, o);
        if (t == 0) sh[0] = z;
    }
    __syncthreads();
    float nrm = sqrtf(sh[0]);
    float sc = 1.f / fmaxf(nrm, 1e-12f);
    float nv = v * sc;
    __nv_bfloat16 h = __float2bfloat16(nv);
    float lo = nv - __bfloat162float(h);
    g_nrm[(size_t)row*DD + t] = nv;
    g_hi[(size_t)row*DD + t] = h;
    g_lo[(size_t)row*DD + t] = __float2bfloat16(lo);
    __nv_bfloat16 xh = __float2bfloat16(v);
    g_chi[(size_t)row*KF + t] = xh;
    g_clo[(size_t)row*KF + t] = __float2bfloat16(v - __bfloat162float(xh));
}

// ---------------- 1b. W hi/lo split ----------------
__global__ void k_wsplit(const float* __restrict__ W) {
    int t = blockIdx.x*256 + threadIdx.x;   // DD*KF = 131072
    float v = W[t];
    __nv_bfloat16 h = __float2bfloat16(v);
    g_whi[t] = h;
    g_wlo[t] = __float2bfloat16(v - __bfloat162float(h));
}

// ---------------- 2. sim tiles via bf16 HMMA 3-split; fused per-chunk top-8 candidates ----------------
__global__ void __launch_bounds__(256, 2) k_sim3() {
    extern __shared__ char smem[];
    uint32_t sb = smem_u32(smem);
    int tid = threadIdx.x;
    int lane = tid & 31, wid = tid >> 5;
    int wm = wid & 3, wn = wid >> 2;

    int t = blockIdx.x;
    int bi = 0;
    while ((bi+1)*(bi+2)/2 <= t) bi++;
    int bj = t - bi*(bi+1)/2;           // bi >= bj
    int b = blockIdx.y;
    int rA = bi*TS2, rB = bj*TS2;

    const __nv_bfloat16* hib = g_hi + (size_t)b*SS*DD;
    const __nv_bfloat16* lob = g_lo + (size_t)b*SS*DD;

    const uint32_t AH = sb, AL = sb + TILE_B, BH = sb + 2*TILE_B, BL = sb + 3*TILE_B;

    float acc[2][8][4];
    #pragma unroll
    for (int i = 0; i < 2; i++)
        #pragma unroll
        for (int j = 0; j < 8; j++)
            #pragma unroll
            for (int q = 0; q < 4; q++) acc[i][j][q] = 0.f;

    int ar = lane & 15, aseg = lane >> 4;
    int br = lane & 7, bsel = lane >> 3;
    int bnoff = (bsel >> 1) * 8, bkoff = (bsel & 1) * 8;

    int lrow = tid >> 1, lcol = (tid & 1) * 32;

    for (int c = 0; c < NCHUNK; c++) {
        int kk = c * KC;
        {
            const uint4* pAh = (const uint4*)(hib + (size_t)(rA+lrow)*DD + kk + lcol);
            const uint4* pAl = (const uint4*)(lob + (size_t)(rA+lrow)*DD + kk + lcol);
            const uint4* pBh = (const uint4*)(hib + (size_t)(rB+lrow)*DD + kk + lcol);
            const uint4* pBl = (const uint4*)(lob + (size_t)(rB+lrow)*DD + kk + lcol);
            uint32_t so = (uint32_t)(lrow*LDA + lcol) * 2;
            #pragma unroll
            for (int q = 0; q < 4; q++) {
                *(uint4*)(smem + (AH - sb) + so + q*16) = pAh[q];
                *(uint4*)(smem + (AL - sb) + so + q*16) = pAl[q];
                *(uint4*)(smem + (BH - sb) + so + q*16) = pBh[q];
                *(uint4*)(smem + (BL - sb) + so + q*16) = pBl[q];
            }
        }
        __syncthreads();

        #pragma unroll
        for (int ks = 0; ks < KC/16; ks++) {
            int kb = ks * 16;
            uint32_t ah[2][4], al[2][4];
            #pragma unroll
            for (int mt = 0; mt < 2; mt++) {
                uint32_t ao = (uint32_t)((wm*32 + mt*16 + ar)*LDA + kb + aseg*8) * 2;
                ldmx4(ah[mt], AH + ao);
                ldmx4(al[mt], AL + ao);
            }
            #pragma unroll
            for (int np = 0; np < 4; np++) {
                uint32_t bo = (uint32_t)((wn*64 + np*16 + bnoff + br)*LDA + kb + bkoff) * 2;
                uint32_t bh[4], bl[4];
                ldmx4(bh, BH + bo);
                ldmx4(bl, BL + bo);
                #pragma unroll
                for (int mt = 0; mt < 2; mt++) {
                    #pragma unroll
                    for (int sub = 0; sub < 2; sub++) {
                        int nt = np*2 + sub;
                        mma16816(acc[mt][nt], ah[mt], bh[sub*2], bh[sub*2+1]);
                        mma16816(acc[mt][nt], ah[mt], bl[sub*2], bl[sub*2+1]);
                        mma16816(acc[mt][nt], al[mt], bh[sub*2], bh[sub*2+1]);
                    }
                }
            }
        }
        __syncthreads();
    }

    // -------- epilogue: pack keys, per-row/per-64-col-chunk top-8 --------
    uint32_t* Ck = (uint32_t*)smem;     // [128][132]
    int fr = lane >> 2, fc = (lane & 3) * 2;

    // orientation 1: rows in tile bi, cols in tile bj (key idx = rB + col)
    #pragma unroll
    for (int mt = 0; mt < 2; mt++) {
        #pragma unroll
        for (int nt = 0; nt < 8; nt++) {
            int r0 = wm*32 + mt*16 + fr;
            int cc = wn*64 + nt*8 + fc;
            int g0 = rA + r0, g1 = rA + r0 + 8;
            int j0 = rB + cc, j1 = rB + cc + 1;
            Ck[r0*132 + cc]       = (g0 == j0) ? 0u : f2key(acc[mt][nt][0], j0);
            Ck[r0*132 + cc+1]     = (g0 == j1) ? 0u : f2key(acc[mt][nt][1], j1);
            Ck[(r0+8)*132 + cc]   = (g1 == j0) ? 0u : f2key(acc[mt][nt][2], j0);
            Ck[(r0+8)*132 + cc+1] = (g1 == j1) ? 0u : f2key(acc[mt][nt][3], j1);
        }
    }
    __syncthreads();
    {
        int row = tid >> 1, half = tid & 1;
        const uint32_t* src = Ck + row*132 + half*64;
        uint32_t tk[8];
        #pragma unroll
        for (int p = 0; p < 8; p++) tk[p] = 0u;
        #pragma unroll 4
        for (int c4 = 0; c4 < 16; c4++) {
            uint4 kk = *(const uint4*)(src + c4*4);
            ins8(tk, kk.x); ins8(tk, kk.y); ins8(tk, kk.z); ins8(tk, kk.w);
        }
        uint32_t* dst = g_cand + ((size_t)(b*SS + rA + row))*256 + (bj*2 + half)*8;
        *(uint4*)(dst)     = make_uint4(tk[0], tk[1], tk[2], tk[3]);
        *(uint4*)(dst + 4) = make_uint4(tk[4], tk[5], tk[6], tk[7]);
    }

    if (bi != bj) {
        __syncthreads();
        // orientation 2: rows in tile bj, cols in tile bi (key idx = rA + row-of-A)
        #pragma unroll
        for (int mt = 0; mt < 2; mt++) {
            #pragma unroll
            for (int nt = 0; nt < 8; nt++) {
                int r0 = wm*32 + mt*16 + fr;
                int cc = wn*64 + nt*8 + fc;
                Ck[cc*132 + r0]       = f2key(acc[mt][nt][0], rA + r0);
                Ck[(cc+1)*132 + r0]   = f2key(acc[mt][nt][1], rA + r0);
                Ck[cc*132 + r0+8]     = f2key(acc[mt][nt][2], rA + r0 + 8);
                Ck[(cc+1)*132 + r0+8] = f2key(acc[mt][nt][3], rA + r0 + 8);
            }
        }
        __syncthreads();
        {
            int row = tid >> 1, half = tid & 1;
            const uint32_t* src = Ck + row*132 + half*64;
            uint32_t tk[8];
            #pragma unroll
            for (int p = 0; p < 8; p++) tk[p] = 0u;
            #pragma unroll 4
            for (int c4 = 0; c4 < 16; c4++) {
                uint4 kk = *(const uint4*)(src + c4*4);
                ins8(tk, kk.x); ins8(tk, kk.y); ins8(tk, kk.z); ins8(tk, kk.w);
            }
            uint32_t* dst = g_cand + ((size_t)(b*SS + rB + row))*256 + (bi*2 + half)*8;
            *(uint4*)(dst)     = make_uint4(tk[0], tk[1], tk[2], tk[3]);
            *(uint4*)(dst + 4) = make_uint4(tk[4], tk[5], tk[6], tk[7]);
        }
    }
}

// ---------------- 3. merge 256 candidate keys -> top-10 -> exact rescore -> top-3 ----------------
// grid RR/8, 256 threads, warp per row
__global__ void __launch_bounds__(256) k_mrg() {
    __shared__ int   cand[8][NCAND];
    __shared__ float ex[8][NCAND];
    int tid = threadIdx.x;
    int lane = tid & 31, wid = tid >> 5;
    int row = blockIdx.x*8 + wid;
    int b = row / SS;

    const uint32_t* src = g_cand + (size_t)row*256;
    uint32_t k[8];
    #pragma unroll
    for (int p = 0; p < 8; p++) k[p] = src[p*32 + lane];   // coalesced

    for (int p = 0; p < NCAND; p++) {
        uint32_t bk = 0u;
        #pragma unroll
        for (int q = 0; q < 8; q++) bk = (k[q] > bk) ? k[q] : bk;
        #pragma unroll
        for (int o = 16; o > 0; o >>= 1) {
            uint32_t ov = __shfl_xor_sync(0xffffffffu, bk, o);
            bk = (ov > bk) ? ov : bk;
        }
        #pragma unroll
        for (int q = 0; q < 8; q++) if (k[q] == bk) k[q] = 0u;   // keys unique: one holder
        if (lane == 0) cand[wid][p] = (int)(bk & 0x7FFu);
    }
    __syncwarp();

    // exact fp32 rescore
    const float* xi = g_nrm + (size_t)row*DD;
    for (int c = 0; c < NCAND; c++) {
        int j = cand[wid][c];
        const float* xj = g_nrm + ((size_t)b*SS + j)*DD;
        float s = 0.f;
        #pragma unroll
        for (int q = 0; q < DD/32; q++) s += xi[lane + q*32] * xj[lane + q*32];
        #pragma unroll
        for (int o = 16; o > 0; o >>= 1) s += __shfl_xor_sync(0xffffffffu, s, o);
        if (lane == 0) ex[wid][c] = s;
    }
    __syncwarp();

    if (lane == 0) {
        bool used[NCAND] = {};
        for (int p = 0; p < 3; p++) {
            float bv = NEG_INF; int bc = -1;
            for (int c = 0; c < NCAND; c++) {
                if (used[c]) continue;
                if (bc < 0 || ex[wid][c] > bv) { bv = ex[wid][c]; bc = c; }
            }
            used[bc] = true;
            g_top[(size_t)row*3 + p] = cand[wid][bc];
        }
    }
}

// ---------------- 4. adjacency bitmask ----------------
__global__ void k_zmask() {
    int t = blockIdx.x*256 + threadIdx.x;
    if (t < RR*(SS/32)) g_mask[t] = 0u;
}

__global__ void k_edges() {
    int t = blockIdx.x*256 + threadIdx.x;
    if (t >= RR*3) return;
    int row = t / 3;
    int j = g_top[t];
    int b = row / SS, i = row % SS;
    atomicOr(&g_mask[(size_t)row*(SS/32) + (j >> 5)], 1u << (j & 31));
    atomicOr(&g_mask[((size_t)b*SS + j)*(SS/32) + (i >> 5)], 1u << (i & 31));
}

// ---------------- 5. neighbor aggregation -> combined[256:512] hi/lo ----------------
__global__ void k_agg(const float* __restrict__ x) {
    int row = blockIdx.x;
    int b = row / SS, i = row % SS;
    __shared__ int   sj[128];
    __shared__ float sw[128];
    __shared__ int   cnt;
    int t = threadIdx.x;
    int lane = t & 31, wid = t >> 5;
    if (t == 0) cnt = 0;
    __syncthreads();
    if (t < SS/32) {
        unsigned w = g_mask[(size_t)row*(SS/32) + t];
        while (w) {
            int bpos = __ffs(w) - 1;
            w &= w - 1;
            int j = t*32 + bpos;
            int p = atomicAdd(&cnt, 1);
            if (p < 128) sj[p] = j;
        }
    }
    __syncthreads();
    int n = min(cnt, 128);

    const float* xi = g_nrm + (size_t)row*DD;
    for (int l = wid; l < n; l += 8) {
        const float* xj = g_nrm + ((size_t)b*SS + sj[l])*DD;
        float s = 0.f;
        #pragma unroll
        for (int q = 0; q < DD/32; q++) s += xi[lane + q*32] * xj[lane + q*32];
        #pragma unroll
        for (int o = 16; o > 0; o >>= 1) s += __shfl_xor_sync(0xffffffffu, s, o);
        if (lane == 0) sw[l] = s;
    }
    __syncthreads();

    float csum = 0.f;
    for (int l = 0; l < n; l++) csum += sw[l];
    float acc = 0.f;
    for (int l = 0; l < n; l++)
        acc += sw[l] * x[((size_t)b*SS + sj[l])*DD + t];
    float mval = acc / fmaxf(csum, 1.0f);
    __nv_bfloat16 h = __float2bfloat16(mval);
    g_chi[(size_t)row*KF + DD + t] = h;
    g_clo[(size_t)row*KF + DD + t] = __float2bfloat16(mval - __bfloat162float(h));
}

// ---------------- 6. projection GEMM via bf16 HMMA 3-split + bias + residual ----------------
__global__ void __launch_bounds__(256, 2) k_out2(const float* __restrict__ x,
                                                 const float* __restrict__ bias) {
    extern __shared__ char smem[];
    uint32_t sb = smem_u32(smem);
    int tid = threadIdx.x;
    int lane = tid & 31, wid = tid >> 5;
    int wm = wid & 3, wn = wid >> 2;        // 4 x 2 warps, warp tile 32x32

    int bx = blockIdx.x;
    int rA = (bx >> 2) * 128, cB = (bx & 3) * 64;

    const uint32_t AH = sb, AL = sb + OUT_A_B, BH = sb + 2*OUT_A_B, BL = sb + 2*OUT_A_B + OUT_B_B;

    float acc[2][4][4];
    #pragma unroll
    for (int i = 0; i < 2; i++)
        #pragma unroll
        for (int j = 0; j < 4; j++)
            #pragma unroll
            for (int q = 0; q < 4; q++) acc[i][j][q] = 0.f;

    int ar = lane & 15, aseg = lane >> 4;
    int br = lane & 7, bsel = lane >> 3;
    int bnoff = (bsel >> 1) * 8, bkoff = (bsel & 1) * 8;

    int lrow = tid >> 1, lcol = (tid & 1) * 32;

    for (int c = 0; c < KF/KC; c++) {       // 8 chunks of 64
        int kk = c * KC;
        {
            const uint4* pAh = (const uint4*)(g_chi + (size_t)(rA+lrow)*KF + kk + lcol);
            const uint4* pAl = (const uint4*)(g_clo + (size_t)(rA+lrow)*KF + kk + lcol);
            uint32_t so = (uint32_t)(lrow*LDA + lcol) * 2;
            #pragma unroll
            for (int q = 0; q < 4; q++) {
                *(uint4*)(smem + (AH - sb) + so + q*16) = pAh[q];
                *(uint4*)(smem + (AL - sb) + so + q*16) = pAl[q];
            }
            if (tid < 128) {
                const uint4* pBh = (const uint4*)(g_whi + (size_t)(cB+lrow)*KF + kk + lcol);
                const uint4* pBl = (const uint4*)(g_wlo + (size_t)(cB+lrow)*KF + kk + lcol);
                #pragma unroll
                for (int q = 0; q < 4; q++) {
                    *(uint4*)(smem + (BH - sb) + so + q*16) = pBh[q];
                    *(uint4*)(smem + (BL - sb) + so + q*16) = pBl[q];
                }
            }
        }
        __syncthreads();

        #pragma unroll
        for (int ks = 0; ks < KC/16; ks++) {
            int kb = ks * 16;
            uint32_t ah[2][4], al[2][4];
            #pragma unroll
            for (int mt = 0; mt < 2; mt++) {
                uint32_t ao = (uint32_t)((wm*32 + mt*16 + ar)*LDA + kb + aseg*8) * 2;
                ldmx4(ah[mt], AH + ao);
                ldmx4(al[mt], AL + ao);
            }
            #pragma unroll
            for (int np = 0; np < 2; np++) {
                uint32_t bo = (uint32_t)((wn*32 + np*16 + bnoff + br)*LDA + kb + bkoff) * 2;
                uint32_t bh[4], bl[4];
                ldmx4(bh, BH + bo);
                ldmx4(bl, BL + bo);
                #pragma unroll
                for (int mt = 0; mt < 2; mt++) {
                    #pragma unroll
                    for (int sub = 0; sub < 2; sub++) {
                        int nt = np*2 + sub;
                        mma16816(acc[mt][nt], ah[mt], bh[sub*2], bh[sub*2+1]);
                        mma16816(acc[mt][nt], ah[mt], bl[sub*2], bl[sub*2+1]);
                        mma16816(acc[mt][nt], al[mt], bh[sub*2], bh[sub*2+1]);
                    }
                }
            }
        }
        __syncthreads();
    }

    int fr = lane >> 2, fc = (lane & 3) * 2;
    #pragma unroll
    for (int mt = 0; mt < 2; mt++) {
        #pragma unroll
        for (int nt = 0; nt < 4; nt++) {
            int r0 = rA + wm*32 + mt*16 + fr;
            int cc = cB + wn*32 + nt*8 + fc;
            g_y[(size_t)r0*DD + cc]       = x[(size_t)r0*DD + cc]       + acc[mt][nt][0] + bias[cc];
            g_y[(size_t)r0*DD + cc+1]     = x[(size_t)r0*DD + cc+1]     + acc[mt][nt][1] + bias[cc+1];
            g_y[(size_t)(r0+8)*DD + cc]   = x[(size_t)(r0+8)*DD + cc]   + acc[mt][nt][2] + bias[cc];
            g_y[(size_t)(r0+8)*DD + cc+1] = x[(size_t)(r0+8)*DD + cc+1] + acc[mt][nt][3] + bias[cc+1];
        }
    }
}

// ---------------- 7. LayerNorm ----------------
__global__ void k_ln(const float* __restrict__ gamma, const float* __restrict__ beta,
                     float* __restrict__ out) {
    int row = blockIdx.x;
    int t = threadIdx.x;
    float v = g_y[(size_t)row*DD + t];
    __shared__ float sh[8];

    float s = v;
    #pragma unroll
    for (int o = 16; o > 0; o >>= 1) s += __shfl_xor_sync(0xffffffffu, s, o);
    if ((t & 31) == 0) sh[t >> 5] = s;
    __syncthreads();
    if (t < 32) {
        float z = (t < 8) ? sh[t] : 0.f;
        #pragma unroll
        for (int o = 4; o > 0; o >>= 1) z += __shfl_xor_sync(0xffffffffu, z, o);
        if (t == 0) sh[0] = z;
    }
    __syncthreads();
    float mu = sh[0] * (1.0f/DD);
    __syncthreads();

    float d = v - mu;
    float s2 = d*d;
    #pragma unroll
    for (int o = 16; o > 0; o >>= 1) s2 += __shfl_xor_sync(0xffffffffu, s2, o);
    if ((t & 31) == 0) sh[t >> 5] = s2;
    __syncthreads();
    if (t < 32) {
        float z = (t < 8) ? sh[t] : 0.f;
        #pragma unroll
        for (int o = 4; o > 0; o >>= 1) z += __shfl_xor_sync(0xffffffffu, z, o);
        if (t == 0) sh[0] = z;
    }
    __syncthreads();
    float var = sh[0] * (1.0f/DD);

    out[(size_t)row*DD + t] = d * rsqrtf(var + 1e-5f) * gamma[t] + beta[t];
}

// ---------------- launch ----------------
extern "C" void kernel_launch(void* const* d_in, const int* in_sizes, int n_in,
                              void* d_out, int out_size) {
    const float* x     = (const float*)d_in[0];
    const float* W     = (const float*)d_in[1];
    const float* bias  = (const float*)d_in[2];
    const float* gamma = (const float*)d_in[3];
    const float* beta  = (const float*)d_in[4];
    float* out = (float*)d_out;

    cudaFuncSetAttribute(k_sim3, cudaFuncAttributeMaxDynamicSharedMemorySize, SIM_SMEM);
    cudaFuncSetAttribute(k_out2, cudaFuncAttributeMaxDynamicSharedMemorySize, OUT_SMEM);

    k_norm<<<RR, 256>>>(x);
    k_wsplit<<<(DD*KF)/256, 256>>>(W);
    k_sim3<<<dim3(TRI2, BB), 256, SIM_SMEM>>>();
    k_mrg<<<RR/8, 256>>>();
    k_zmask<<<(RR*(SS/32) + 255)/256, 256>>>();
    k_edges<<<(RR*3 + 255)/256, 256>>>();
    k_agg<<<RR, 256>>>(x);
    k_out2<<<(RR/128)*4, 256, OUT_SMEM>>>(x, bias);
    k_ln<<<RR, 256>>>(gamma, beta, out);
}

// round 12
// speedup vs baseline: 2.1326x; 1.2195x over previous
#include <cuda_runtime.h>
#include <cuda_bf16.h>
#include <cuda_fp16.h>
#include <math.h>
#include <stdint.h>

#define BB 8
#define SS 2048
#define DD 256
#define RR (BB*SS)          // 16384 rows total
#define NEG_INF -1.0e30f

// ----- HMMA sim tiling -----
#define TS2 128
#define NT2 (SS/TS2)                 // 16
#define TRI2 (NT2*(NT2+1)/2)         // 136
#define KC 64
#define NCHUNK (DD/KC)               // 4
#define LDA 72                       // padded smem row stride (2B elems)
#define TILE_B (128*LDA*2)           // 18432 bytes per operand tile
#define SIM_STAGE_B (2*TILE_B)       // A+B per stage = 36864
#define SIM_SMEM (2*SIM_STAGE_B)     // 73728 (covers key buffer 128*132*4=67584)

#define NCAND 10                     // merge width (rescored exactly)

// ----- HMMA out tiling -----
#define KF (2*DD)                    // 512
#define OUT_A_B (128*LDA*2)          // 18432
#define OUT_B_B (64*LDA*2)           // 9216
#define OUT_SMEM (2*OUT_A_B + 2*OUT_B_B)   // 55296

// ---------------- static scratch ----------------
__device__ float    g_nrm[(size_t)RR*DD];            // 16 MB exact normalized rows
__device__ __half   g_f16[(size_t)RR*DD];            // 8 MB fp16 normalized rows
__device__ uint32_t g_cand[(size_t)RR*256];          // 16.8 MB packed candidate keys
__device__ int      g_top[(size_t)RR*3];
__device__ unsigned g_mask[(size_t)RR*(SS/32)];      // 4 MB
__device__ __nv_bfloat16 g_chi[(size_t)RR*KF];       // 16 MB combined hi
__device__ __nv_bfloat16 g_clo[(size_t)RR*KF];       // 16 MB combined lo
__device__ __nv_bfloat16 g_whi[(size_t)DD*KF];       // 256 KB
__device__ __nv_bfloat16 g_wlo[(size_t)DD*KF];       // 256 KB
__device__ float    g_y[(size_t)RR*DD];              // 16 MB

__device__ __forceinline__ uint32_t smem_u32(const void* p) {
    uint32_t a;
    asm("{ .reg .u64 t; cvta.to.shared.u64 t, %1; cvt.u32.u64 %0, t; }" : "=r"(a) : "l"(p));
    return a;
}
__device__ __forceinline__ void ldmx4(uint32_t* r, uint32_t addr) {
    asm volatile("ldmatrix.sync.aligned.m8n8.x4.shared.b16 {%0,%1,%2,%3}, [%4];"
        : "=r"(r[0]), "=r"(r[1]), "=r"(r[2]), "=r"(r[3]) : "r"(addr));
}
__device__ __forceinline__ void mma16816(float* c, const uint32_t* a, uint32_t b0, uint32_t b1) {
    asm volatile("mma.sync.aligned.m16n8k16.row.col.f32.bf16.bf16.f32 "
        "{%0,%1,%2,%3}, {%4,%5,%6,%7}, {%8,%9}, {%0,%1,%2,%3};"
        : "+f"(c[0]), "+f"(c[1]), "+f"(c[2]), "+f"(c[3])
        : "r"(a[0]), "r"(a[1]), "r"(a[2]), "r"(a[3]), "r"(b0), "r"(b1));
}
__device__ __forceinline__ void mma16816h(float* c, const uint32_t* a, uint32_t b0, uint32_t b1) {
    asm volatile("mma.sync.aligned.m16n8k16.row.col.f32.f16.f16.f32 "
        "{%0,%1,%2,%3}, {%4,%5,%6,%7}, {%8,%9}, {%0,%1,%2,%3};"
        : "+f"(c[0]), "+f"(c[1]), "+f"(c[2]), "+f"(c[3])
        : "r"(a[0]), "r"(a[1]), "r"(a[2]), "r"(a[3]), "r"(b0), "r"(b1));
}
__device__ __forceinline__ void cpa16(uint32_t dst, const void* src) {
    asm volatile("cp.async.ca.shared.global [%0], [%1], 16;" :: "r"(dst), "l"(src));
}
#define CP_COMMIT() asm volatile("cp.async.commit_group;" ::: "memory")
#define CP_WAIT(n)  asm volatile("cp.async.wait_group %0;" :: "n"(n) : "memory")

// order-preserving float -> uint, top 21 bits kept, 11-bit index packed low
__device__ __forceinline__ uint32_t f2key(float f, int j) {
    uint32_t u = __float_as_uint(f);
    u ^= (uint32_t)((int)u >> 31) | 0x80000000u;
    return (u & 0xFFFFF800u) | (uint32_t)j;
}
// sorted-descending top-8 insert (guarded)
__device__ __forceinline__ void ins8(uint32_t* tk, uint32_t k) {
    if (k > tk[7]) {
        #pragma unroll
        for (int p = 7; p >= 1; p--)
            tk[p] = (k > tk[p-1]) ? tk[p-1] : (k > tk[p] ? k : tk[p]);
        if (k > tk[0]) tk[0] = k;
    }
}

// ---------------- 1. row L2-normalize -> fp32 + fp16; raw x -> combined[0:256] ----------------
__global__ void k_norm(const float* __restrict__ x) {
    int row = blockIdx.x;
    int t = threadIdx.x;
    float v = x[(size_t)row*DD + t];
    __shared__ float sh[8];
    float s = v*v;
    #pragma unroll
    for (int o = 16; o > 0; o >>= 1) s += __shfl_xor_sync(0xffffffffu, s, o);
    if ((t & 31) == 0) sh[t >> 5] = s;
    __syncthreads();
    if (t < 32) {
        float z = (t < 8) ? sh[t] : 0.f;
        #pragma unroll
        for (int o = 4; o > 0; o >>= 1) z += __shfl_xor_sync(0xffffffffu, z, o);
        if (t == 0) sh[0] = z;
    }
    __syncthreads();
    float nrm = sqrtf(sh[0]);
    float sc = 1.f / fmaxf(nrm, 1e-12f);
    float nv = v * sc;
    g_nrm[(size_t)row*DD + t] = nv;
    g_f16[(size_t)row*DD + t] = __float2half(nv);
    __nv_bfloat16 xh = __float2bfloat16(v);
    g_chi[(size_t)row*KF + t] = xh;
    g_clo[(size_t)row*KF + t] = __float2bfloat16(v - __bfloat162float(xh));
}

// ---------------- 1b. W hi/lo split ----------------
__global__ void k_wsplit(const float* __restrict__ W) {
    int t = blockIdx.x*256 + threadIdx.x;   // DD*KF = 131072
    float v = W[t];
    __nv_bfloat16 h = __float2bfloat16(v);
    g_whi[t] = h;
    g_wlo[t] = __float2bfloat16(v - __bfloat162float(h));
}

// ---------------- 2. sim tiles via single fp16 HMMA, cp.async 2-stage; fused top-8 candidates ----------------
__global__ void __launch_bounds__(256, 2) k_sim3() {
    extern __shared__ char smem[];
    uint32_t sb = smem_u32(smem);
    int tid = threadIdx.x;
    int lane = tid & 31, wid = tid >> 5;
    int wm = wid & 3, wn = wid >> 2;

    int t = blockIdx.x;
    int bi = 0;
    while ((bi+1)*(bi+2)/2 <= t) bi++;
    int bj = t - bi*(bi+1)/2;           // bi >= bj
    int b = blockIdx.y;
    int rA = bi*TS2, rB = bj*TS2;

    const __half* hb = g_f16 + (size_t)b*SS*DD;

    float acc[2][8][4];
    #pragma unroll
    for (int i = 0; i < 2; i++)
        #pragma unroll
        for (int j = 0; j < 8; j++)
            #pragma unroll
            for (int q = 0; q < 4; q++) acc[i][j][q] = 0.f;

    int ar = lane & 15, aseg = lane >> 4;
    int br = lane & 7, bsel = lane >> 3;
    int bnoff = (bsel >> 1) * 8, bkoff = (bsel & 1) * 8;

    int lrow = tid >> 1, lcol = (tid & 1) * 32;
    uint32_t so = (uint32_t)(lrow*LDA + lcol) * 2;

    // prologue: chunk 0 -> stage 0
    {
        const char* gA = (const char*)(hb + (size_t)(rA+lrow)*DD + lcol);
        const char* gB = (const char*)(hb + (size_t)(rB+lrow)*DD + lcol);
        uint32_t dA = sb + so, dB = sb + TILE_B + so;
        #pragma unroll
        for (int q = 0; q < 4; q++) { cpa16(dA + q*16, gA + q*16); cpa16(dB + q*16, gB + q*16); }
        CP_COMMIT();
    }

    for (int c = 0; c < NCHUNK; c++) {
        if (c + 1 < NCHUNK) {
            int kk = (c+1) * KC;
            int s = (c+1) & 1;
            const char* gA = (const char*)(hb + (size_t)(rA+lrow)*DD + kk + lcol);
            const char* gB = (const char*)(hb + (size_t)(rB+lrow)*DD + kk + lcol);
            uint32_t dA = sb + s*SIM_STAGE_B + so, dB = dA + TILE_B;
            #pragma unroll
            for (int q = 0; q < 4; q++) { cpa16(dA + q*16, gA + q*16); cpa16(dB + q*16, gB + q*16); }
            CP_COMMIT();
            CP_WAIT(1);
        } else {
            CP_WAIT(0);
        }
        __syncthreads();

        uint32_t stA = sb + (c & 1)*SIM_STAGE_B;
        uint32_t stB = stA + TILE_B;
        #pragma unroll
        for (int ks = 0; ks < KC/16; ks++) {
            int kb = ks * 16;
            uint32_t ah[2][4];
            #pragma unroll
            for (int mt = 0; mt < 2; mt++) {
                uint32_t ao = (uint32_t)((wm*32 + mt*16 + ar)*LDA + kb + aseg*8) * 2;
                ldmx4(ah[mt], stA + ao);
            }
            #pragma unroll
            for (int np = 0; np < 4; np++) {
                uint32_t bo = (uint32_t)((wn*64 + np*16 + bnoff + br)*LDA + kb + bkoff) * 2;
                uint32_t bh[4];
                ldmx4(bh, stB + bo);
                #pragma unroll
                for (int mt = 0; mt < 2; mt++)
                    #pragma unroll
                    for (int sub = 0; sub < 2; sub++)
                        mma16816h(acc[mt][np*2 + sub], ah[mt], bh[sub*2], bh[sub*2+1]);
            }
        }
        __syncthreads();
    }

    // -------- epilogue: pack keys, per-row/per-64-col-chunk top-8 --------
    uint32_t* Ck = (uint32_t*)smem;     // [128][132]
    int fr = lane >> 2, fc = (lane & 3) * 2;

    // orientation 1: rows in tile bi, cols in tile bj (key idx = rB + col)
    #pragma unroll
    for (int mt = 0; mt < 2; mt++) {
        #pragma unroll
        for (int nt = 0; nt < 8; nt++) {
            int r0 = wm*32 + mt*16 + fr;
            int cc = wn*64 + nt*8 + fc;
            int g0 = rA + r0, g1 = rA + r0 + 8;
            int j0 = rB + cc, j1 = rB + cc + 1;
            Ck[r0*132 + cc]       = (g0 == j0) ? 0u : f2key(acc[mt][nt][0], j0);
            Ck[r0*132 + cc+1]     = (g0 == j1) ? 0u : f2key(acc[mt][nt][1], j1);
            Ck[(r0+8)*132 + cc]   = (g1 == j0) ? 0u : f2key(acc[mt][nt][2], j0);
            Ck[(r0+8)*132 + cc+1] = (g1 == j1) ? 0u : f2key(acc[mt][nt][3], j1);
        }
    }
    __syncthreads();
    {
        int row = tid >> 1, half = tid & 1;
        const uint32_t* src = Ck + row*132 + half*64;
        uint32_t tk[8];
        #pragma unroll
        for (int p = 0; p < 8; p++) tk[p] = 0u;
        #pragma unroll 4
        for (int c4 = 0; c4 < 16; c4++) {
            uint4 kk = *(const uint4*)(src + c4*4);
            ins8(tk, kk.x); ins8(tk, kk.y); ins8(tk, kk.z); ins8(tk, kk.w);
        }
        uint32_t* dst = g_cand + ((size_t)(b*SS + rA + row))*256 + (bj*2 + half)*8;
        *(uint4*)(dst)     = make_uint4(tk[0], tk[1], tk[2], tk[3]);
        *(uint4*)(dst + 4) = make_uint4(tk[4], tk[5], tk[6], tk[7]);
    }

    if (bi != bj) {
        __syncthreads();
        // orientation 2: rows in tile bj, cols in tile bi (key idx = rA + row-of-A)
        #pragma unroll
        for (int mt = 0; mt < 2; mt++) {
            #pragma unroll
            for (int nt = 0; nt < 8; nt++) {
                int r0 = wm*32 + mt*16 + fr;
                int cc = wn*64 + nt*8 + fc;
                Ck[cc*132 + r0]       = f2key(acc[mt][nt][0], rA + r0);
                Ck[(cc+1)*132 + r0]   = f2key(acc[mt][nt][1], rA + r0);
                Ck[cc*132 + r0+8]     = f2key(acc[mt][nt][2], rA + r0 + 8);
                Ck[(cc+1)*132 + r0+8] = f2key(acc[mt][nt][3], rA + r0 + 8);
            }
        }
        __syncthreads();
        {
            int row = tid >> 1, half = tid & 1;
            const uint32_t* src = Ck + row*132 + half*64;
            uint32_t tk[8];
            #pragma unroll
            for (int p = 0; p < 8; p++) tk[p] = 0u;
            #pragma unroll 4
            for (int c4 = 0; c4 < 16; c4++) {
                uint4 kk = *(const uint4*)(src + c4*4);
                ins8(tk, kk.x); ins8(tk, kk.y); ins8(tk, kk.z); ins8(tk, kk.w);
            }
            uint32_t* dst = g_cand + ((size_t)(b*SS + rB + row))*256 + (bi*2 + half)*8;
            *(uint4*)(dst)     = make_uint4(tk[0], tk[1], tk[2], tk[3]);
            *(uint4*)(dst + 4) = make_uint4(tk[4], tk[5], tk[6], tk[7]);
        }
    }
}

// ---------------- 3. merge 256 candidate keys -> top-10 -> exact rescore -> top-3 ----------------
// grid RR/8, 256 threads, warp per row
__global__ void __launch_bounds__(256) k_mrg() {
    __shared__ int   cand[8][NCAND];
    __shared__ float ex[8][NCAND];
    int tid = threadIdx.x;
    int lane = tid & 31, wid = tid >> 5;
    int row = blockIdx.x*8 + wid;
    int b = row / SS;

    const uint32_t* src = g_cand + (size_t)row*256;
    uint32_t k[8];
    #pragma unroll
    for (int p = 0; p < 8; p++) k[p] = src[p*32 + lane];   // coalesced

    for (int p = 0; p < NCAND; p++) {
        uint32_t bk = 0u;
        #pragma unroll
        for (int q = 0; q < 8; q++) bk = (k[q] > bk) ? k[q] : bk;
        #pragma unroll
        for (int o = 16; o > 0; o >>= 1) {
            uint32_t ov = __shfl_xor_sync(0xffffffffu, bk, o);
            bk = (ov > bk) ? ov : bk;
        }
        #pragma unroll
        for (int q = 0; q < 8; q++) if (k[q] == bk) k[q] = 0u;   // keys unique: one holder
        if (lane == 0) cand[wid][p] = (int)(bk & 0x7FFu);
    }
    __syncwarp();

    // exact fp32 rescore
    const float* xi = g_nrm + (size_t)row*DD;
    for (int c = 0; c < NCAND; c++) {
        int j = cand[wid][c];
        const float* xj = g_nrm + ((size_t)b*SS + j)*DD;
        float s = 0.f;
        #pragma unroll
        for (int q = 0; q < DD/32; q++) s += xi[lane + q*32] * xj[lane + q*32];
        #pragma unroll
        for (int o = 16; o > 0; o >>= 1) s += __shfl_xor_sync(0xffffffffu, s, o);
        if (lane == 0) ex[wid][c] = s;
    }
    __syncwarp();

    if (lane == 0) {
        bool used[NCAND] = {};
        for (int p = 0; p < 3; p++) {
            float bv = NEG_INF; int bc = -1;
            for (int c = 0; c < NCAND; c++) {
                if (used[c]) continue;
                if (bc < 0 || ex[wid][c] > bv) { bv = ex[wid][c]; bc = c; }
            }
            used[bc] = true;
            g_top[(size_t)row*3 + p] = cand[wid][bc];
        }
    }
}

// ---------------- 4. adjacency bitmask ----------------
__global__ void k_zmask() {
    int t = blockIdx.x*256 + threadIdx.x;
    if (t < RR*(SS/32)) g_mask[t] = 0u;
}

__global__ void k_edges() {
    int t = blockIdx.x*256 + threadIdx.x;
    if (t >= RR*3) return;
    int row = t / 3;
    int j = g_top[t];
    int b = row / SS, i = row % SS;
    atomicOr(&g_mask[(size_t)row*(SS/32) + (j >> 5)], 1u << (j & 31));
    atomicOr(&g_mask[((size_t)b*SS + j)*(SS/32) + (i >> 5)], 1u << (i & 31));
}

// ---------------- 5. neighbor aggregation -> combined[256:512] hi/lo ----------------
__global__ void k_agg(const float* __restrict__ x) {
    int row = blockIdx.x;
    int b = row / SS, i = row % SS;
    __shared__ int   sj[128];
    __shared__ float sw[128];
    __shared__ int   cnt;
    int t = threadIdx.x;
    int lane = t & 31, wid = t >> 5;
    if (t == 0) cnt = 0;
    __syncthreads();
    if (t < SS/32) {
        unsigned w = g_mask[(size_t)row*(SS/32) + t];
        while (w) {
            int bpos = __ffs(w) - 1;
            w &= w - 1;
            int j = t*32 + bpos;
            int p = atomicAdd(&cnt, 1);
            if (p < 128) sj[p] = j;
        }
    }
    __syncthreads();
    int n = min(cnt, 128);

    const float* xi = g_nrm + (size_t)row*DD;
    for (int l = wid; l < n; l += 8) {
        const float* xj = g_nrm + ((size_t)b*SS + sj[l])*DD;
        float s = 0.f;
        #pragma unroll
        for (int q = 0; q < DD/32; q++) s += xi[lane + q*32] * xj[lane + q*32];
        #pragma unroll
        for (int o = 16; o > 0; o >>= 1) s += __shfl_xor_sync(0xffffffffu, s, o);
        if (lane == 0) sw[l] = s;
    }
    __syncthreads();

    float csum = 0.f;
    for (int l = 0; l < n; l++) csum += sw[l];
    float acc = 0.f;
    for (int l = 0; l < n; l++)
        acc += sw[l] * x[((size_t)b*SS + sj[l])*DD + t];
    float mval = acc / fmaxf(csum, 1.0f);
    __nv_bfloat16 h = __float2bfloat16(mval);
    g_chi[(size_t)row*KF + DD + t] = h;
    g_clo[(size_t)row*KF + DD + t] = __float2bfloat16(mval - __bfloat162float(h));
}

// ---------------- 6. projection GEMM via bf16 HMMA 3-split + bias + residual ----------------
__global__ void __launch_bounds__(256, 2) k_out2(const float* __restrict__ x,
                                                 const float* __restrict__ bias) {
    extern __shared__ char smem[];
    uint32_t sb = smem_u32(smem);
    int tid = threadIdx.x;
    int lane = tid & 31, wid = tid >> 5;
    int wm = wid & 3, wn = wid >> 2;        // 4 x 2 warps, warp tile 32x32

    int bx = blockIdx.x;
    int rA = (bx >> 2) * 128, cB = (bx & 3) * 64;

    const uint32_t AH = sb, AL = sb + OUT_A_B, BH = sb + 2*OUT_A_B, BL = sb + 2*OUT_A_B + OUT_B_B;

    float acc[2][4][4];
    #pragma unroll
    for (int i = 0; i < 2; i++)
        #pragma unroll
        for (int j = 0; j < 4; j++)
            #pragma unroll
            for (int q = 0; q < 4; q++) acc[i][j][q] = 0.f;

    int ar = lane & 15, aseg = lane >> 4;
    int br = lane & 7, bsel = lane >> 3;
    int bnoff = (bsel >> 1) * 8, bkoff = (bsel & 1) * 8;

    int lrow = tid >> 1, lcol = (tid & 1) * 32;

    for (int c = 0; c < KF/KC; c++) {       // 8 chunks of 64
        int kk = c * KC;
        {
            const uint4* pAh = (const uint4*)(g_chi + (size_t)(rA+lrow)*KF + kk + lcol);
            const uint4* pAl = (const uint4*)(g_clo + (size_t)(rA+lrow)*KF + kk + lcol);
            uint32_t so = (uint32_t)(lrow*LDA + lcol) * 2;
            #pragma unroll
            for (int q = 0; q < 4; q++) {
                *(uint4*)(smem + (AH - sb) + so + q*16) = pAh[q];
                *(uint4*)(smem + (AL - sb) + so + q*16) = pAl[q];
            }
            if (tid < 128) {
                const uint4* pBh = (const uint4*)(g_whi + (size_t)(cB+lrow)*KF + kk + lcol);
                const uint4* pBl = (const uint4*)(g_wlo + (size_t)(cB+lrow)*KF + kk + lcol);
                #pragma unroll
                for (int q = 0; q < 4; q++) {
                    *(uint4*)(smem + (BH - sb) + so + q*16) = pBh[q];
                    *(uint4*)(smem + (BL - sb) + so + q*16) = pBl[q];
                }
            }
        }
        __syncthreads();

        #pragma unroll
        for (int ks = 0; ks < KC/16; ks++) {
            int kb = ks * 16;
            uint32_t ah[2][4], al[2][4];
            #pragma unroll
            for (int mt = 0; mt < 2; mt++) {
                uint32_t ao = (uint32_t)((wm*32 + mt*16 + ar)*LDA + kb + aseg*8) * 2;
                ldmx4(ah[mt], AH + ao);
                ldmx4(al[mt], AL + ao);
            }
            #pragma unroll
            for (int np = 0; np < 2; np++) {
                uint32_t bo = (uint32_t)((wn*32 + np*16 + bnoff + br)*LDA + kb + bkoff) * 2;
                uint32_t bh[4], bl[4];
                ldmx4(bh, BH + bo);
                ldmx4(bl, BL + bo);
                #pragma unroll
                for (int mt = 0; mt < 2; mt++) {
                    #pragma unroll
                    for (int sub = 0; sub < 2; sub++) {
                        int nt = np*2 + sub;
                        mma16816(acc[mt][nt], ah[mt], bh[sub*2], bh[sub*2+1]);
                        mma16816(acc[mt][nt], ah[mt], bl[sub*2], bl[sub*2+1]);
                        mma16816(acc[mt][nt], al[mt], bh[sub*2], bh[sub*2+1]);
                    }
                }
            }
        }
        __syncthreads();
    }

    int fr = lane >> 2, fc = (lane & 3) * 2;
    #pragma unroll
    for (int mt = 0; mt < 2; mt++) {
        #pragma unroll
        for (int nt = 0; nt < 4; nt++) {
            int r0 = rA + wm*32 + mt*16 + fr;
            int cc = cB + wn*32 + nt*8 + fc;
            g_y[(size_t)r0*DD + cc]       = x[(size_t)r0*DD + cc]       + acc[mt][nt][0] + bias[cc];
            g_y[(size_t)r0*DD + cc+1]     = x[(size_t)r0*DD + cc+1]     + acc[mt][nt][1] + bias[cc+1];
            g_y[(size_t)(r0+8)*DD + cc]   = x[(size_t)(r0+8)*DD + cc]   + acc[mt][nt][2] + bias[cc];
            g_y[(size_t)(r0+8)*DD + cc+1] = x[(size_t)(r0+8)*DD + cc+1] + acc[mt][nt][3] + bias[cc+1];
        }
    }
}

// ---------------- 7. LayerNorm ----------------
__global__ void k_ln(const float* __restrict__ gamma, const float* __restrict__ beta,
                     float* __restrict__ out) {
    int row = blockIdx.x;
    int t = threadIdx.x;
    float v = g_y[(size_t)row*DD + t];
    __shared__ float sh[8];

    float s = v;
    #pragma unroll
    for (int o = 16; o > 0; o >>= 1) s += __shfl_xor_sync(0xffffffffu, s, o);
    if ((t & 31) == 0) sh[t >> 5] = s;
    __syncthreads();
    if (t < 32) {
        float z = (t < 8) ? sh[t] : 0.f;
        #pragma unroll
        for (int o = 4; o > 0; o >>= 1) z += __shfl_xor_sync(0xffffffffu, z, o);
        if (t == 0) sh[0] = z;
    }
    __syncthreads();
    float mu = sh[0] * (1.0f/DD);
    __syncthreads();

    float d = v - mu;
    float s2 = d*d;
    #pragma unroll
    for (int o = 16; o > 0; o >>= 1) s2 += __shfl_xor_sync(0xffffffffu, s2, o);
    if ((t & 31) == 0) sh[t >> 5] = s2;
    __syncthreads();
    if (t < 32) {
        float z = (t < 8) ? sh[t] : 0.f;
        #pragma unroll
        for (int o = 4; o > 0; o >>= 1) z += __shfl_xor_sync(0xffffffffu, z, o);
        if (t == 0) sh[0] = z;
    }
    __syncthreads();
    float var = sh[0] * (1.0f/DD);

    out[(size_t)row*DD + t] = d * rsqrtf(var + 1e-5f) * gamma[t] + beta[t];
}

// ---------------- launch ----------------
extern "C" void kernel_launch(void* const* d_in, const int* in_sizes, int n_in,
                              void* d_out, int out_size) {
    const float* x     = (const float*)d_in[0];
    const float* W     = (const float*)d_in[1];
    const float* bias  = (const float*)d_in[2];
    const float* gamma = (const float*)d_in[3];
    const float* beta  = (const float*)d_in[4];
    float* out = (float*)d_out;

    cudaFuncSetAttribute(k_sim3, cudaFuncAttributeMaxDynamicSharedMemorySize, SIM_SMEM);
    cudaFuncSetAttribute(k_out2, cudaFuncAttributeMaxDynamicSharedMemorySize, OUT_SMEM);

    k_norm<<<RR, 256>>>(x);
    k_wsplit<<<(DD*KF)/256, 256>>>(W);
    k_sim3<<<dim3(TRI2, BB), 256, SIM_SMEM>>>();
    k_mrg<<<RR/8, 256>>>();
    k_zmask<<<(RR*(SS/32) + 255)/256, 256>>>();
    k_edges<<<(RR*3 + 255)/256, 256>>>();
    k_agg<<<RR, 256>>>(x);
    k_out2<<<(RR/128)*4, 256, OUT_SMEM>>>(x, bias);
    k_ln<<<RR, 256>>>(gamma, beta, out);
}